// round 2
// baseline (speedup 1.0000x reference)
#include <cuda_runtime.h>
#include <math.h>

#define NN_ 1536
#define DD_ 768
#define HH_ 64
#define PLANE (NN_ * NN_)
#define KSPLIT 12

typedef unsigned long long u64;

// Scratch (fully overwritten every launch -> graph-replay safe)
__device__ float g_part[KSPLIT * NN_ * 128]; // k-split partials of E@[W1a|W1b]
__device__ float g_A[NN_ * HH_];             // ha - g
__device__ float g_B[NN_ * HH_];             // hb + g + b1
__device__ float g_pv[NN_ * 6];              // pos(3), vel(3)

// ---- f32x2 packed helpers (sm_100+) --------------------------------------
__device__ __forceinline__ u64 pack2(float lo, float hi) {
    u64 r; asm("mov.b64 %0,{%1,%2};" : "=l"(r) : "f"(lo), "f"(hi)); return r;
}
__device__ __forceinline__ void unpack2(u64 v, float& lo, float& hi) {
    asm("mov.b64 {%0,%1},%2;" : "=f"(lo), "=f"(hi) : "l"(v));
}
__device__ __forceinline__ u64 fma2(u64 a, u64 b, u64 c) {
    u64 d; asm("fma.rn.f32x2 %0,%1,%2,%3;" : "=l"(d) : "l"(a), "l"(b), "l"(c)); return d;
}
__device__ __forceinline__ u64 add2(u64 a, u64 b) {
    u64 d; asm("add.rn.f32x2 %0,%1,%2;" : "=l"(d) : "l"(a), "l"(b)); return d;
}

// ---------------------------------------------------------------------------
// Kernel 1: partial GEMM. grid (48, KSPLIT), 256 threads.
// Block (ib, ks): rows ib*32..+31, k-chunk ks*64..+63, 128 output cols
// (cols 0..63 = W1a contribution, 64..127 = W1b contribution).
// ---------------------------------------------------------------------------
__global__ __launch_bounds__(256) void gemm_partial_kernel(
    const float* __restrict__ E, const float* __restrict__ W1)
{
    __shared__ __align__(16) float sE[32 * 17];   // 32 rows x 16 k, pad 17
    __shared__ __align__(16) float sW[16 * 128];  // 16 k x 128 h2

    const int t  = threadIdx.x;
    const int ib = blockIdx.x;
    const int ks = blockIdx.y;
    const int lane32 = t & 31;   // h-group (float4 col index)
    const int ig     = t >> 5;   // i-group (4 rows each)

    float4 acc0 = make_float4(0.f, 0.f, 0.f, 0.f);
    float4 acc1 = acc0, acc2 = acc0, acc3 = acc0;

    for (int kt = 0; kt < 4; ++kt) {
        const int kbase = ks * 64 + kt * 16;
        for (int idx = t; idx < 512; idx += 256) {
            int r = idx >> 4, c = idx & 15;
            sE[r * 17 + c] = E[(ib * 32 + r) * DD_ + kbase + c];
        }
        for (int idx = t; idx < 2048; idx += 256) {
            int kk = idx >> 7, h2 = idx & 127;
            float v = (h2 < 64) ? W1[(kbase + kk) * 64 + h2]
                                : W1[(DD_ + kbase + kk) * 64 + (h2 - 64)];
            sW[kk * 128 + h2] = v;
        }
        __syncthreads();
#pragma unroll
        for (int kk = 0; kk < 16; ++kk) {
            float4 w = reinterpret_cast<const float4*>(sW)[kk * 32 + lane32];
            float e0 = sE[(ig * 4 + 0) * 17 + kk];
            float e1 = sE[(ig * 4 + 1) * 17 + kk];
            float e2 = sE[(ig * 4 + 2) * 17 + kk];
            float e3 = sE[(ig * 4 + 3) * 17 + kk];
            acc0.x = fmaf(e0, w.x, acc0.x); acc0.y = fmaf(e0, w.y, acc0.y);
            acc0.z = fmaf(e0, w.z, acc0.z); acc0.w = fmaf(e0, w.w, acc0.w);
            acc1.x = fmaf(e1, w.x, acc1.x); acc1.y = fmaf(e1, w.y, acc1.y);
            acc1.z = fmaf(e1, w.z, acc1.z); acc1.w = fmaf(e1, w.w, acc1.w);
            acc2.x = fmaf(e2, w.x, acc2.x); acc2.y = fmaf(e2, w.y, acc2.y);
            acc2.z = fmaf(e2, w.z, acc2.z); acc2.w = fmaf(e2, w.w, acc2.w);
            acc3.x = fmaf(e3, w.x, acc3.x); acc3.y = fmaf(e3, w.y, acc3.y);
            acc3.z = fmaf(e3, w.z, acc3.z); acc3.w = fmaf(e3, w.w, acc3.w);
        }
        __syncthreads();
    }

    float4* dst = reinterpret_cast<float4*>(g_part) + (size_t)ks * (NN_ * 32);
    int ibase = ib * 32 + ig * 4;
    dst[(ibase + 0) * 32 + lane32] = acc0;
    dst[(ibase + 1) * 32 + lane32] = acc1;
    dst[(ibase + 2) * 32 + lane32] = acc2;
    dst[(ibase + 3) * 32 + lane32] = acc3;
}

// ---------------------------------------------------------------------------
// Kernel 2: reduce partials + fold geometry terms. grid 1536, 64 threads.
// ---------------------------------------------------------------------------
__global__ __launch_bounds__(64) void fold_kernel(
    const float* __restrict__ pos, const float* __restrict__ prev,
    const float* __restrict__ W1, const float* __restrict__ b1)
{
    const int i = blockIdx.x;
    const int h = threadIdx.x;

    float suma = 0.f, sumb = 0.f;
#pragma unroll
    for (int s = 0; s < KSPLIT; ++s) {
        suma += g_part[(size_t)s * (NN_ * 128) + i * 128 + h];
        sumb += g_part[(size_t)s * (NN_ * 128) + i * 128 + 64 + h];
    }
    float px = pos[i * 3 + 0], py = pos[i * 3 + 1], pz = pos[i * 3 + 2];
    float vx = px - prev[i * 3 + 0];
    float vy = py - prev[i * 3 + 1];
    float vz = pz - prev[i * 3 + 2];

    const float* Ws = W1 + 2 * DD_ * 64;  // W1s rows (8 x 64)
    float g = px * Ws[0 * 64 + h] + py * Ws[1 * 64 + h] + pz * Ws[2 * 64 + h]
            + vx * Ws[4 * 64 + h] + vy * Ws[5 * 64 + h] + vz * Ws[6 * 64 + h]
            + py * Ws[7 * 64 + h];

    g_A[i * 64 + h] = suma - g;
    g_B[i * 64 + h] = sumb + g + b1[h];

    if (h == 0) {
        g_pv[i * 6 + 0] = px; g_pv[i * 6 + 1] = py; g_pv[i * 6 + 2] = pz;
        g_pv[i * 6 + 3] = vx; g_pv[i * 6 + 4] = vy; g_pv[i * 6 + 5] = vz;
    }
}

// ---------------------------------------------------------------------------
// Kernel 3: pairwise, f32x2 packed. grid (48, 48), block (16, 16).
// Thread micro-tile: i in {ty, ty+16}, j in {tx, tx+16}; the two j's are
// packed into f32x2 lanes. ReLU via exact identity relu(t)*w2=(t+|t|)*(w2/2).
// ---------------------------------------------------------------------------
__global__ __launch_bounds__(256) void pair_kernel(
    const float* __restrict__ W1, const float* __restrict__ W2,
    const float* __restrict__ b2, float* __restrict__ out)
{
    __shared__ __align__(16) u64 sAp[32 * 66];  // {a,a} duplicated, row pad 66
    __shared__ __align__(16) u64 sBp[16 * 66];  // {b(j=tx), b(j=tx+16)}
    __shared__ __align__(16) u64 sW2p[256];     // {w2/2, w2/2}, [h*4+k]
    __shared__ __align__(16) u64 sW3p[64];      // {w3, w3}
    __shared__ float sPVi[32 * 6];
    __shared__ float sPVj[32 * 6];

    const int tx = threadIdx.x, ty = threadIdx.y;
    const int t  = ty * 16 + tx;
    const int i0 = blockIdx.y * 32;
    const int j0 = blockIdx.x * 32;

    const float4* gA4 = reinterpret_cast<const float4*>(g_A);
    const float4* gB4 = reinterpret_cast<const float4*>(g_B);

    // A tile: 32 rows x 16 float4, duplicate each value into both halves
    for (int idx = t; idx < 512; idx += 256) {
        int r = idx >> 4, c = idx & 15;
        float4 v = gA4[(i0 + r) * 16 + c];
        u64* d = &sAp[r * 66 + c * 4];
        d[0] = pack2(v.x, v.x); d[1] = pack2(v.y, v.y);
        d[2] = pack2(v.z, v.z); d[3] = pack2(v.w, v.w);
    }
    // B tile: pack rows (r, r+16)
    for (int idx = t; idx < 256; idx += 256) {
        int r = idx >> 4, c = idx & 15;
        float4 v0 = gB4[(j0 + r) * 16 + c];
        float4 v1 = gB4[(j0 + r + 16) * 16 + c];
        u64* d = &sBp[r * 66 + c * 4];
        d[0] = pack2(v0.x, v1.x); d[1] = pack2(v0.y, v1.y);
        d[2] = pack2(v0.z, v1.z); d[3] = pack2(v0.w, v1.w);
    }
    {   // W2/2 broadcast-packed
        float w = 0.5f * W2[t];             // t = h*4+k, matches layout
        sW2p[t] = pack2(w, w);
        if (t < 64) {
            float w3 = W1[(2 * DD_ + 3) * 64 + t];
            sW3p[t] = pack2(w3, w3);
        }
    }
    for (int idx = t; idx < 192; idx += 256) {
        sPVi[idx] = g_pv[i0 * 6 + idx];
        sPVj[idx] = g_pv[j0 * 6 + idx];
    }
    __syncthreads();

    // geometry for the 4 pairs (pq = p*2+q; q0 -> j=tx, q1 -> j=tx+16)
    float dist[4], clos[4], vdif[4];
#pragma unroll
    for (int p = 0; p < 2; ++p) {
        int ri = ty + p * 16;
        float pix = sPVi[ri * 6 + 0], piy = sPVi[ri * 6 + 1], piz = sPVi[ri * 6 + 2];
        float vix = sPVi[ri * 6 + 3], viy = sPVi[ri * 6 + 4], viz = sPVi[ri * 6 + 5];
#pragma unroll
        for (int q = 0; q < 2; ++q) {
            int rj = tx + q * 16;
            float rpx = sPVj[rj * 6 + 0] - pix;
            float rpy = sPVj[rj * 6 + 1] - piy;
            float rpz = sPVj[rj * 6 + 2] - piz;
            float rvx = sPVj[rj * 6 + 3] - vix;
            float rvy = sPVj[rj * 6 + 4] - viy;
            float rvz = sPVj[rj * 6 + 5] - viz;
            float d = sqrtf(rpx * rpx + rpy * rpy + rpz * rpz);
            float dot = rpx * rvx + rpy * rvy + rpz * rvz;
            int pq = p * 2 + q;
            dist[pq] = d;
            clos[pq] = -dot / fmaxf(d, 1e-6f);
            vdif[pq] = rpy;
        }
    }

    u64 dpk[2];
    dpk[0] = pack2(dist[0], dist[1]);
    dpk[1] = pack2(dist[2], dist[3]);

    u64 acc[2][4];
#pragma unroll
    for (int p = 0; p < 2; ++p)
#pragma unroll
        for (int k = 0; k < 4; ++k) acc[p][k] = 0ULL;

#pragma unroll 4
    for (int h4 = 0; h4 < 16; ++h4) {
        const ulonglong2* pa0 = reinterpret_cast<const ulonglong2*>(&sAp[ty * 66 + h4 * 4]);
        const ulonglong2* pa1 = reinterpret_cast<const ulonglong2*>(&sAp[(ty + 16) * 66 + h4 * 4]);
        const ulonglong2* pb  = reinterpret_cast<const ulonglong2*>(&sBp[tx * 66 + h4 * 4]);
        const ulonglong2* pw3 = reinterpret_cast<const ulonglong2*>(&sW3p[h4 * 4]);
        const ulonglong2* pw2 = reinterpret_cast<const ulonglong2*>(&sW2p[h4 * 16]);

        u64 a[2][4], b[4], w3[4], w2[16];
        ulonglong2 u0, u1;
        u0 = pa0[0]; u1 = pa0[1];
        a[0][0] = u0.x; a[0][1] = u0.y; a[0][2] = u1.x; a[0][3] = u1.y;
        u0 = pa1[0]; u1 = pa1[1];
        a[1][0] = u0.x; a[1][1] = u0.y; a[1][2] = u1.x; a[1][3] = u1.y;
        u0 = pb[0]; u1 = pb[1];
        b[0] = u0.x; b[1] = u0.y; b[2] = u1.x; b[3] = u1.y;
        u0 = pw3[0]; u1 = pw3[1];
        w3[0] = u0.x; w3[1] = u0.y; w3[2] = u1.x; w3[3] = u1.y;
#pragma unroll
        for (int kk = 0; kk < 8; ++kk) {
            ulonglong2 w = pw2[kk];
            w2[2 * kk] = w.x; w2[2 * kk + 1] = w.y;
        }
#pragma unroll
        for (int hh = 0; hh < 4; ++hh) {
#pragma unroll
            for (int p = 0; p < 2; ++p) {
                u64 tt = fma2(dpk[p], w3[hh], add2(a[p][hh], b[hh]));
                u64 uu = add2(tt, tt & 0x7FFFFFFF7FFFFFFFULL);  // 2*relu(t)
                acc[p][0] = fma2(uu, w2[hh * 4 + 0], acc[p][0]);
                acc[p][1] = fma2(uu, w2[hh * 4 + 1], acc[p][1]);
                acc[p][2] = fma2(uu, w2[hh * 4 + 2], acc[p][2]);
                acc[p][3] = fma2(uu, w2[hh * 4 + 3], acc[p][3]);
            }
        }
    }

    const float b20 = __ldg(&b2[0]), b21 = __ldg(&b2[1]);
    const float b22 = __ldg(&b2[2]), b23 = __ldg(&b2[3]);

#pragma unroll
    for (int p = 0; p < 2; ++p) {
        float lq0[4], lq1[4];
        unpack2(acc[p][0], lq0[0], lq1[0]);
        unpack2(acc[p][1], lq0[1], lq1[1]);
        unpack2(acc[p][2], lq0[2], lq1[2]);
        unpack2(acc[p][3], lq0[3], lq1[3]);
#pragma unroll
        for (int q = 0; q < 2; ++q) {
            const int pq = p * 2 + q;
            const float* lv = q ? lq1 : lq0;
            float l0 = lv[0] + b20;
            float l1 = lv[1] + b21;
            float l2 = lv[2] + b22;
            float l3 = lv[3] + b23;
            float m = fmaxf(fmaxf(l0, l1), fmaxf(l2, l3));
            float sum = __expf(l0 - m) + __expf(l1 - m) + __expf(l2 - m) + __expf(l3 - m);
            float conf = 1.0f / sum;
            int best = 0; float bm = l0;
            if (l1 > bm) { bm = l1; best = 1; }
            if (l2 > bm) { bm = l2; best = 2; }
            if (l3 > bm) { bm = l3; best = 3; }

            float d = dist[pq], c = clos[pq], v = vdif[pq];
            bool near  = d < 0.25f;
            bool appr  = !near && (c > 0.05f);
            bool flee  = !near && !appr && (c < -0.05f);
            bool above = !near && !appr && !flee && (fabsf(v) > 0.3f) && (d < 0.5f);

            int rt = near ? 0 : (appr ? 1 : (flee ? 2 : (above ? 3 : best)));
            float co = conf;
            if (near)              co = fmaxf(co, 0.8f);
            else if (appr || flee) co = fmaxf(co, 0.6f);
            else if (above)        co = fmaxf(co, 0.5f);

            int ig = i0 + ty + p * 16;
            int jg = j0 + tx + q * 16;
            size_t off = (size_t)ig * NN_ + jg;
            out[off]             = (float)rt;
            out[PLANE + off]     = co;
            out[2 * PLANE + off] = (jg > ig && co > 0.3f) ? 1.0f : 0.0f;
        }
    }
}

extern "C" void kernel_launch(void* const* d_in, const int* in_sizes, int n_in,
                              void* d_out, int out_size)
{
    const float* E    = (const float*)d_in[0];
    const float* pos  = (const float*)d_in[1];
    const float* prev = (const float*)d_in[2];
    const float* W1   = (const float*)d_in[3];
    const float* b1   = (const float*)d_in[4];
    const float* W2   = (const float*)d_in[5];
    const float* b2   = (const float*)d_in[6];
    float* out = (float*)d_out;

    gemm_partial_kernel<<<dim3(48, KSPLIT), 256>>>(E, W1);
    fold_kernel<<<NN_, 64>>>(pos, prev, W1, b1);
    pair_kernel<<<dim3(48, 48), dim3(16, 16)>>>(W1, W2, b2, out);
}

// round 3
// speedup vs baseline: 1.1012x; 1.1012x over previous
#include <cuda_runtime.h>
#include <math.h>

#define NN_ 1536
#define DD_ 768
#define HH_ 64
#define PLANE (NN_ * NN_)
#define KSPLIT 24

// Scratch (fully overwritten every launch -> graph-replay safe)
__device__ float g_part[KSPLIT * NN_ * 128]; // k-split partials of E@[W1a|W1b]
__device__ float g_A[NN_ * HH_];             // ha - g
__device__ float g_B[NN_ * HH_];             // hb + g + b1
__device__ float g_pv[NN_ * 6];              // pos(3), vel(3)

// ---------------------------------------------------------------------------
// Kernel 1: partial GEMM. grid (48, KSPLIT), 256 threads.
// Block (ib, ks): rows ib*32..+31, k-chunk ks*32..+31, 128 output cols
// (cols 0..63 = W1a contribution, 64..127 = W1b contribution).
// ---------------------------------------------------------------------------
__global__ __launch_bounds__(256) void gemm_partial_kernel(
    const float* __restrict__ E, const float* __restrict__ W1)
{
    __shared__ __align__(16) float sE[32 * 17];   // 32 rows x 16 k, pad 17
    __shared__ __align__(16) float sW[16 * 128];  // 16 k x 128 h2

    const int t  = threadIdx.x;
    const int ib = blockIdx.x;
    const int ks = blockIdx.y;
    const int lane32 = t & 31;   // h-group (float4 col index)
    const int ig     = t >> 5;   // i-group (4 rows each)

    float4 acc0 = make_float4(0.f, 0.f, 0.f, 0.f);
    float4 acc1 = acc0, acc2 = acc0, acc3 = acc0;

    for (int kt = 0; kt < 2; ++kt) {
        const int kbase = ks * 32 + kt * 16;
        for (int idx = t; idx < 512; idx += 256) {
            int r = idx >> 4, c = idx & 15;
            sE[r * 17 + c] = E[(ib * 32 + r) * DD_ + kbase + c];
        }
        for (int idx = t; idx < 2048; idx += 256) {
            int kk = idx >> 7, h2 = idx & 127;
            float v = (h2 < 64) ? W1[(kbase + kk) * 64 + h2]
                                : W1[(DD_ + kbase + kk) * 64 + (h2 - 64)];
            sW[kk * 128 + h2] = v;
        }
        __syncthreads();
#pragma unroll
        for (int kk = 0; kk < 16; ++kk) {
            float4 w = reinterpret_cast<const float4*>(sW)[kk * 32 + lane32];
            float e0 = sE[(ig * 4 + 0) * 17 + kk];
            float e1 = sE[(ig * 4 + 1) * 17 + kk];
            float e2 = sE[(ig * 4 + 2) * 17 + kk];
            float e3 = sE[(ig * 4 + 3) * 17 + kk];
            acc0.x = fmaf(e0, w.x, acc0.x); acc0.y = fmaf(e0, w.y, acc0.y);
            acc0.z = fmaf(e0, w.z, acc0.z); acc0.w = fmaf(e0, w.w, acc0.w);
            acc1.x = fmaf(e1, w.x, acc1.x); acc1.y = fmaf(e1, w.y, acc1.y);
            acc1.z = fmaf(e1, w.z, acc1.z); acc1.w = fmaf(e1, w.w, acc1.w);
            acc2.x = fmaf(e2, w.x, acc2.x); acc2.y = fmaf(e2, w.y, acc2.y);
            acc2.z = fmaf(e2, w.z, acc2.z); acc2.w = fmaf(e2, w.w, acc2.w);
            acc3.x = fmaf(e3, w.x, acc3.x); acc3.y = fmaf(e3, w.y, acc3.y);
            acc3.z = fmaf(e3, w.z, acc3.z); acc3.w = fmaf(e3, w.w, acc3.w);
        }
        __syncthreads();
    }

    float4* dst = reinterpret_cast<float4*>(g_part) + (size_t)ks * (NN_ * 32);
    int ibase = ib * 32 + ig * 4;
    dst[(ibase + 0) * 32 + lane32] = acc0;
    dst[(ibase + 1) * 32 + lane32] = acc1;
    dst[(ibase + 2) * 32 + lane32] = acc2;
    dst[(ibase + 3) * 32 + lane32] = acc3;
}

// ---------------------------------------------------------------------------
// Kernel 2: reduce partials + fold geometry terms. grid 1536, 64 threads.
// ---------------------------------------------------------------------------
__global__ __launch_bounds__(64) void fold_kernel(
    const float* __restrict__ pos, const float* __restrict__ prev,
    const float* __restrict__ W1, const float* __restrict__ b1)
{
    const int i = blockIdx.x;
    const int h = threadIdx.x;

    float suma = 0.f, sumb = 0.f;
#pragma unroll
    for (int s = 0; s < KSPLIT; ++s) {
        suma += g_part[(size_t)s * (NN_ * 128) + i * 128 + h];
        sumb += g_part[(size_t)s * (NN_ * 128) + i * 128 + 64 + h];
    }
    float px = pos[i * 3 + 0], py = pos[i * 3 + 1], pz = pos[i * 3 + 2];
    float vx = px - prev[i * 3 + 0];
    float vy = py - prev[i * 3 + 1];
    float vz = pz - prev[i * 3 + 2];

    const float* Ws = W1 + 2 * DD_ * 64;  // W1s rows (8 x 64)
    float g = px * Ws[0 * 64 + h] + py * Ws[1 * 64 + h] + pz * Ws[2 * 64 + h]
            + vx * Ws[4 * 64 + h] + vy * Ws[5 * 64 + h] + vz * Ws[6 * 64 + h]
            + py * Ws[7 * 64 + h];

    g_A[i * 64 + h] = suma - g;
    g_B[i * 64 + h] = sumb + g + b1[h];

    if (h == 0) {
        g_pv[i * 6 + 0] = px; g_pv[i * 6 + 1] = py; g_pv[i * 6 + 2] = pz;
        g_pv[i * 6 + 3] = vx; g_pv[i * 6 + 4] = vy; g_pv[i * 6 + 5] = vz;
    }
}

// ---------------------------------------------------------------------------
// Kernel 3: pairwise. grid (48, 48), block (16, 16). Each thread: 2x2 strided
// micro-tile i in {ty, ty+16}, j in {tx, tx+16}.
// Logits computed as softmax-invariant differences: delta_k = l_k - l_0 using
// W2d[h][k] = W2[h][k+1] - W2[h][0]  (3 accumulators per pair, not 4).
// ---------------------------------------------------------------------------
__global__ __launch_bounds__(256) void pair_kernel(
    const float* __restrict__ W1, const float* __restrict__ W2,
    const float* __restrict__ b2, float* __restrict__ out)
{
    __shared__ __align__(16) float sA[32 * 68];   // rows padded to 68 floats
    __shared__ __align__(16) float sB[32 * 68];
    __shared__ __align__(16) float4 sW2d[64];     // (d1,d2,d3,0) per h
    __shared__ __align__(16) float sW3[64];
    __shared__ float sPVi[32 * 6];
    __shared__ float sPVj[32 * 6];

    const int tx = threadIdx.x, ty = threadIdx.y;
    const int t  = ty * 16 + tx;
    const int i0 = blockIdx.y * 32;
    const int j0 = blockIdx.x * 32;

    for (int idx = t; idx < 512; idx += 256) {
        int r = idx >> 4, c = idx & 15;
        reinterpret_cast<float4*>(sA)[r * 17 + c] =
            reinterpret_cast<const float4*>(g_A)[(i0 + r) * 16 + c];
        reinterpret_cast<float4*>(sB)[r * 17 + c] =
            reinterpret_cast<const float4*>(g_B)[(j0 + r) * 16 + c];
    }
    if (t < 64) {
        float w0 = W2[t * 4 + 0];
        sW2d[t] = make_float4(W2[t * 4 + 1] - w0, W2[t * 4 + 2] - w0,
                              W2[t * 4 + 3] - w0, 0.f);
        sW3[t] = W1[(2 * DD_ + 3) * 64 + t];  // w3 = W1s row 3 (distance)
    }
    for (int idx = t; idx < 192; idx += 256) {
        sPVi[idx] = g_pv[i0 * 6 + idx];
        sPVj[idx] = g_pv[j0 * 6 + idx];
    }
    __syncthreads();

    // geometry for the 4 pairs
    float dist[4], clos[4], vdif[4];
#pragma unroll
    for (int p = 0; p < 2; ++p) {
        int ri = ty + p * 16;
        float pix = sPVi[ri * 6 + 0], piy = sPVi[ri * 6 + 1], piz = sPVi[ri * 6 + 2];
        float vix = sPVi[ri * 6 + 3], viy = sPVi[ri * 6 + 4], viz = sPVi[ri * 6 + 5];
#pragma unroll
        for (int q = 0; q < 2; ++q) {
            int rj = tx + q * 16;
            float rpx = sPVj[rj * 6 + 0] - pix;
            float rpy = sPVj[rj * 6 + 1] - piy;
            float rpz = sPVj[rj * 6 + 2] - piz;
            float rvx = sPVj[rj * 6 + 3] - vix;
            float rvy = sPVj[rj * 6 + 4] - viy;
            float rvz = sPVj[rj * 6 + 5] - viz;
            float d = sqrtf(rpx * rpx + rpy * rpy + rpz * rpz);
            float dot = rpx * rvx + rpy * rvy + rpz * rvz;
            int pq = p * 2 + q;
            dist[pq] = d;
            clos[pq] = -dot / fmaxf(d, 1e-6f);
            vdif[pq] = rpy;
        }
    }

    float acc1[4] = {0.f, 0.f, 0.f, 0.f};   // delta_1 accum per pair
    float acc2[4] = {0.f, 0.f, 0.f, 0.f};   // delta_2
    float acc3[4] = {0.f, 0.f, 0.f, 0.f};   // delta_3

    const float4* A4  = reinterpret_cast<const float4*>(sA);
    const float4* B4  = reinterpret_cast<const float4*>(sB);
    const float4* W34 = reinterpret_cast<const float4*>(sW3);

#pragma unroll 4
    for (int h4 = 0; h4 < 16; ++h4) {
        float4 af[2], bf[2];
        af[0] = A4[ty * 17 + h4];
        af[1] = A4[(ty + 16) * 17 + h4];
        bf[0] = B4[tx * 17 + h4];
        bf[1] = B4[(tx + 16) * 17 + h4];
        float4 w3v = W34[h4];
        float4 wd0 = sW2d[h4 * 4 + 0];
        float4 wd1 = sW2d[h4 * 4 + 1];
        float4 wd2 = sW2d[h4 * 4 + 2];
        float4 wd3 = sW2d[h4 * 4 + 3];

        const float aw[2][4] = {{af[0].x, af[0].y, af[0].z, af[0].w},
                                {af[1].x, af[1].y, af[1].z, af[1].w}};
        const float bw[2][4] = {{bf[0].x, bf[0].y, bf[0].z, bf[0].w},
                                {bf[1].x, bf[1].y, bf[1].z, bf[1].w}};
        const float w3a[4] = {w3v.x, w3v.y, w3v.z, w3v.w};
        const float4 wda[4] = {wd0, wd1, wd2, wd3};

#pragma unroll
        for (int hh = 0; hh < 4; ++hh) {
            const float w3h = w3a[hh];
            const float4 wd = wda[hh];
#pragma unroll
            for (int p = 0; p < 2; ++p) {
#pragma unroll
                for (int q = 0; q < 2; ++q) {
                    const int pq = p * 2 + q;
                    float tt = fmaf(dist[pq], w3h, aw[p][hh] + bw[q][hh]);
                    float r  = fmaxf(tt, 0.f);
                    acc1[pq] = fmaf(r, wd.x, acc1[pq]);
                    acc2[pq] = fmaf(r, wd.y, acc2[pq]);
                    acc3[pq] = fmaf(r, wd.z, acc3[pq]);
                }
            }
        }
    }

    const float db1 = __ldg(&b2[1]) - __ldg(&b2[0]);
    const float db2 = __ldg(&b2[2]) - __ldg(&b2[0]);
    const float db3 = __ldg(&b2[3]) - __ldg(&b2[0]);

#pragma unroll
    for (int p = 0; p < 2; ++p) {
#pragma unroll
        for (int q = 0; q < 2; ++q) {
            const int pq = p * 2 + q;
            float d1 = acc1[pq] + db1;
            float d2 = acc2[pq] + db2;
            float d3 = acc3[pq] + db3;
            // delta_0 = 0
            float m = fmaxf(fmaxf(0.f, d1), fmaxf(d2, d3));
            float sum = __expf(0.f - m) + __expf(d1 - m)
                      + __expf(d2 - m) + __expf(d3 - m);
            float conf = 1.0f / sum;
            int best = 0; float bm = 0.f;
            if (d1 > bm) { bm = d1; best = 1; }
            if (d2 > bm) { bm = d2; best = 2; }
            if (d3 > bm) { bm = d3; best = 3; }

            float d = dist[pq], c = clos[pq], v = vdif[pq];
            bool near  = d < 0.25f;
            bool appr  = !near && (c > 0.05f);
            bool flee  = !near && !appr && (c < -0.05f);
            bool above = !near && !appr && !flee && (fabsf(v) > 0.3f) && (d < 0.5f);

            int rt = near ? 0 : (appr ? 1 : (flee ? 2 : (above ? 3 : best)));
            float co = conf;
            if (near)              co = fmaxf(co, 0.8f);
            else if (appr || flee) co = fmaxf(co, 0.6f);
            else if (above)        co = fmaxf(co, 0.5f);

            int ig = i0 + ty + p * 16;
            int jg = j0 + tx + q * 16;
            size_t off = (size_t)ig * NN_ + jg;
            out[off]             = (float)rt;
            out[PLANE + off]     = co;
            out[2 * PLANE + off] = (jg > ig && co > 0.3f) ? 1.0f : 0.0f;
        }
    }
}

extern "C" void kernel_launch(void* const* d_in, const int* in_sizes, int n_in,
                              void* d_out, int out_size)
{
    const float* E    = (const float*)d_in[0];
    const float* pos  = (const float*)d_in[1];
    const float* prev = (const float*)d_in[2];
    const float* W1   = (const float*)d_in[3];
    const float* b1   = (const float*)d_in[4];
    const float* W2   = (const float*)d_in[5];
    const float* b2   = (const float*)d_in[6];
    float* out = (float*)d_out;

    gemm_partial_kernel<<<dim3(48, KSPLIT), 256>>>(E, W1);
    fold_kernel<<<NN_, 64>>>(pos, prev, W1, b1);
    pair_kernel<<<dim3(48, 48), dim3(16, 16)>>>(W1, W2, b2, out);
}

// round 4
// speedup vs baseline: 1.1975x; 1.0874x over previous
#include <cuda_runtime.h>
#include <math.h>

#define NN_ 1536
#define DD_ 768
#define HH_ 64
#define PLANE (NN_ * NN_)
#define KSPLIT 12

// Scratch (fully overwritten every launch -> graph-replay safe)
__device__ float g_part[KSPLIT * NN_ * 128]; // k-split partials of E@[W1a|W1b]
__device__ float g_A[NN_ * HH_];             // ha - g
__device__ float g_B[NN_ * HH_];             // hb + g + b1
__device__ float g_pv[NN_ * 6];              // pos(3), vel(3)

// ---------------------------------------------------------------------------
// Kernel 1: partial GEMM. grid (24, KSPLIT), 256 threads.
// Block (rb, ks): rows rb*64..+63, k-chunk ks*64..+63, 128 output cols
// (cols 0..63 = W1a contribution, 64..127 = W1b contribution).
// Per thread: 8 rows x 4 cols. E tile stored k-major (transposed) so the 8
// e-values per kk are two broadcast LDS.128.
// ---------------------------------------------------------------------------
__global__ __launch_bounds__(256) void gemm_partial_kernel(
    const float* __restrict__ E, const float* __restrict__ W1)
{
    __shared__ __align__(16) float sET[16 * 68];  // [kk][row], 64 rows + pad 4
    __shared__ __align__(16) float sW[16 * 128];  // [kk][h2]

    const int t    = threadIdx.x;
    const int rb   = blockIdx.x;
    const int ks   = blockIdx.y;
    const int lane = t & 31;   // col group: cols lane*4..+3
    const int wrp  = t >> 5;   // row group: rows wrp*8..+7

    float4 acc[8];
#pragma unroll
    for (int r = 0; r < 8; ++r) acc[r] = make_float4(0.f, 0.f, 0.f, 0.f);

    const float4* E4 = reinterpret_cast<const float4*>(E);
    const float4* W4g = reinterpret_cast<const float4*>(W1);

    for (int kt = 0; kt < 4; ++kt) {
        const int kbase = ks * 64 + kt * 16;

        // fill sET (transposed): thread -> one float4 of E (row, 4 k-vals)
        {
            int row = t >> 2, c4 = t & 3;
            float4 v = E4[((rb * 64 + row) * DD_ + kbase) / 4 + c4];
            sET[(c4 * 4 + 0) * 68 + row] = v.x;
            sET[(c4 * 4 + 1) * 68 + row] = v.y;
            sET[(c4 * 4 + 2) * 68 + row] = v.z;
            sET[(c4 * 4 + 3) * 68 + row] = v.w;
        }
        // fill sW: 512 float4, 2 per thread
#pragma unroll
        for (int idx = t; idx < 512; idx += 256) {
            int kk = idx >> 5, c4 = idx & 31;
            float4 v = (c4 < 16) ? W4g[((kbase + kk) * 64) / 4 + c4]
                                 : W4g[((DD_ + kbase + kk) * 64) / 4 + (c4 - 16)];
            reinterpret_cast<float4*>(sW)[kk * 32 + c4] = v;
        }
        __syncthreads();

        const float4* sET4 = reinterpret_cast<const float4*>(sET);
        const float4* sW4  = reinterpret_cast<const float4*>(sW);
#pragma unroll
        for (int kk = 0; kk < 16; ++kk) {
            float4 w  = sW4[kk * 32 + lane];
            float4 e0 = sET4[kk * 17 + wrp * 2 + 0];  // rows wrp*8..+3
            float4 e1 = sET4[kk * 17 + wrp * 2 + 1];  // rows wrp*8+4..+7
            const float ev[8] = {e0.x, e0.y, e0.z, e0.w, e1.x, e1.y, e1.z, e1.w};
#pragma unroll
            for (int r = 0; r < 8; ++r) {
                acc[r].x = fmaf(ev[r], w.x, acc[r].x);
                acc[r].y = fmaf(ev[r], w.y, acc[r].y);
                acc[r].z = fmaf(ev[r], w.z, acc[r].z);
                acc[r].w = fmaf(ev[r], w.w, acc[r].w);
            }
        }
        __syncthreads();
    }

    float4* dst = reinterpret_cast<float4*>(g_part) + (size_t)ks * (NN_ * 32);
    const int rbase = rb * 64 + wrp * 8;
#pragma unroll
    for (int r = 0; r < 8; ++r)
        dst[(rbase + r) * 32 + lane] = acc[r];
}

// ---------------------------------------------------------------------------
// Kernel 2: reduce partials + fold geometry terms. grid 384, block (64,4).
// ---------------------------------------------------------------------------
__global__ __launch_bounds__(256) void fold_kernel(
    const float* __restrict__ pos, const float* __restrict__ prev,
    const float* __restrict__ W1, const float* __restrict__ b1)
{
    const int i = blockIdx.x * 4 + threadIdx.y;
    const int h = threadIdx.x;

    float suma = 0.f, sumb = 0.f;
#pragma unroll
    for (int s = 0; s < KSPLIT; ++s) {
        suma += g_part[(size_t)s * (NN_ * 128) + i * 128 + h];
        sumb += g_part[(size_t)s * (NN_ * 128) + i * 128 + 64 + h];
    }
    float px = pos[i * 3 + 0], py = pos[i * 3 + 1], pz = pos[i * 3 + 2];
    float vx = px - prev[i * 3 + 0];
    float vy = py - prev[i * 3 + 1];
    float vz = pz - prev[i * 3 + 2];

    const float* Ws = W1 + 2 * DD_ * 64;  // W1s rows (8 x 64)
    float g = px * Ws[0 * 64 + h] + py * Ws[1 * 64 + h] + pz * Ws[2 * 64 + h]
            + vx * Ws[4 * 64 + h] + vy * Ws[5 * 64 + h] + vz * Ws[6 * 64 + h]
            + py * Ws[7 * 64 + h];

    g_A[i * 64 + h] = suma - g;
    g_B[i * 64 + h] = sumb + g + b1[h];

    if (h == 0) {
        g_pv[i * 6 + 0] = px; g_pv[i * 6 + 1] = py; g_pv[i * 6 + 2] = pz;
        g_pv[i * 6 + 3] = vx; g_pv[i * 6 + 4] = vy; g_pv[i * 6 + 5] = vz;
    }
}

// ---------------------------------------------------------------------------
// Kernel 3: pairwise. grid (48, 48), block (16, 16). Each thread: 2x2 strided
// micro-tile i in {ty, ty+16}, j in {tx, tx+16}.
// Logits as softmax-invariant differences: delta_k = l_k - l_0 using
// W2d[h][k] = W2[h][k+1] - W2[h][0]  (3 accumulators per pair, not 4).
// ---------------------------------------------------------------------------
__global__ __launch_bounds__(256) void pair_kernel(
    const float* __restrict__ W1, const float* __restrict__ W2,
    const float* __restrict__ b2, float* __restrict__ out)
{
    __shared__ __align__(16) float sA[32 * 68];   // rows padded to 68 floats
    __shared__ __align__(16) float sB[32 * 68];
    __shared__ __align__(16) float4 sW2d[64];     // (d1,d2,d3,0) per h
    __shared__ __align__(16) float sW3[64];
    __shared__ float sPVi[32 * 6];
    __shared__ float sPVj[32 * 6];

    const int tx = threadIdx.x, ty = threadIdx.y;
    const int t  = ty * 16 + tx;
    const int i0 = blockIdx.y * 32;
    const int j0 = blockIdx.x * 32;

    for (int idx = t; idx < 512; idx += 256) {
        int r = idx >> 4, c = idx & 15;
        reinterpret_cast<float4*>(sA)[r * 17 + c] =
            reinterpret_cast<const float4*>(g_A)[(i0 + r) * 16 + c];
        reinterpret_cast<float4*>(sB)[r * 17 + c] =
            reinterpret_cast<const float4*>(g_B)[(j0 + r) * 16 + c];
    }
    if (t < 64) {
        float w0 = W2[t * 4 + 0];
        sW2d[t] = make_float4(W2[t * 4 + 1] - w0, W2[t * 4 + 2] - w0,
                              W2[t * 4 + 3] - w0, 0.f);
        sW3[t] = W1[(2 * DD_ + 3) * 64 + t];  // w3 = W1s row 3 (distance)
    }
    for (int idx = t; idx < 192; idx += 256) {
        sPVi[idx] = g_pv[i0 * 6 + idx];
        sPVj[idx] = g_pv[j0 * 6 + idx];
    }
    __syncthreads();

    // geometry for the 4 pairs
    float dist[4], clos[4], vdif[4];
#pragma unroll
    for (int p = 0; p < 2; ++p) {
        int ri = ty + p * 16;
        float pix = sPVi[ri * 6 + 0], piy = sPVi[ri * 6 + 1], piz = sPVi[ri * 6 + 2];
        float vix = sPVi[ri * 6 + 3], viy = sPVi[ri * 6 + 4], viz = sPVi[ri * 6 + 5];
#pragma unroll
        for (int q = 0; q < 2; ++q) {
            int rj = tx + q * 16;
            float rpx = sPVj[rj * 6 + 0] - pix;
            float rpy = sPVj[rj * 6 + 1] - piy;
            float rpz = sPVj[rj * 6 + 2] - piz;
            float rvx = sPVj[rj * 6 + 3] - vix;
            float rvy = sPVj[rj * 6 + 4] - viy;
            float rvz = sPVj[rj * 6 + 5] - viz;
            float d = sqrtf(rpx * rpx + rpy * rpy + rpz * rpz);
            float dot = rpx * rvx + rpy * rvy + rpz * rvz;
            int pq = p * 2 + q;
            dist[pq] = d;
            clos[pq] = -dot / fmaxf(d, 1e-6f);
            vdif[pq] = rpy;
        }
    }

    float acc1[4] = {0.f, 0.f, 0.f, 0.f};
    float acc2[4] = {0.f, 0.f, 0.f, 0.f};
    float acc3[4] = {0.f, 0.f, 0.f, 0.f};

    const float4* A4  = reinterpret_cast<const float4*>(sA);
    const float4* B4  = reinterpret_cast<const float4*>(sB);
    const float4* W34 = reinterpret_cast<const float4*>(sW3);

#pragma unroll 4
    for (int h4 = 0; h4 < 16; ++h4) {
        float4 af[2], bf[2];
        af[0] = A4[ty * 17 + h4];
        af[1] = A4[(ty + 16) * 17 + h4];
        bf[0] = B4[tx * 17 + h4];
        bf[1] = B4[(tx + 16) * 17 + h4];
        float4 w3v = W34[h4];
        float4 wd0 = sW2d[h4 * 4 + 0];
        float4 wd1 = sW2d[h4 * 4 + 1];
        float4 wd2 = sW2d[h4 * 4 + 2];
        float4 wd3 = sW2d[h4 * 4 + 3];

        const float aw[2][4] = {{af[0].x, af[0].y, af[0].z, af[0].w},
                                {af[1].x, af[1].y, af[1].z, af[1].w}};
        const float bw[2][4] = {{bf[0].x, bf[0].y, bf[0].z, bf[0].w},
                                {bf[1].x, bf[1].y, bf[1].z, bf[1].w}};
        const float w3a[4] = {w3v.x, w3v.y, w3v.z, w3v.w};
        const float4 wda[4] = {wd0, wd1, wd2, wd3};

#pragma unroll
        for (int hh = 0; hh < 4; ++hh) {
            const float w3h = w3a[hh];
            const float4 wd = wda[hh];
#pragma unroll
            for (int p = 0; p < 2; ++p) {
#pragma unroll
                for (int q = 0; q < 2; ++q) {
                    const int pq = p * 2 + q;
                    float tt = fmaf(dist[pq], w3h, aw[p][hh] + bw[q][hh]);
                    float r  = fmaxf(tt, 0.f);
                    acc1[pq] = fmaf(r, wd.x, acc1[pq]);
                    acc2[pq] = fmaf(r, wd.y, acc2[pq]);
                    acc3[pq] = fmaf(r, wd.z, acc3[pq]);
                }
            }
        }
    }

    const float db1 = __ldg(&b2[1]) - __ldg(&b2[0]);
    const float db2 = __ldg(&b2[2]) - __ldg(&b2[0]);
    const float db3 = __ldg(&b2[3]) - __ldg(&b2[0]);

#pragma unroll
    for (int p = 0; p < 2; ++p) {
#pragma unroll
        for (int q = 0; q < 2; ++q) {
            const int pq = p * 2 + q;
            float d1 = acc1[pq] + db1;
            float d2 = acc2[pq] + db2;
            float d3 = acc3[pq] + db3;
            float m = fmaxf(fmaxf(0.f, d1), fmaxf(d2, d3));
            float sum = __expf(0.f - m) + __expf(d1 - m)
                      + __expf(d2 - m) + __expf(d3 - m);
            float conf = __fdividef(1.0f, sum);
            int best = 0; float bm = 0.f;
            if (d1 > bm) { bm = d1; best = 1; }
            if (d2 > bm) { bm = d2; best = 2; }
            if (d3 > bm) { bm = d3; best = 3; }

            float d = dist[pq], c = clos[pq], v = vdif[pq];
            bool near  = d < 0.25f;
            bool appr  = !near && (c > 0.05f);
            bool flee  = !near && !appr && (c < -0.05f);
            bool above = !near && !appr && !flee && (fabsf(v) > 0.3f) && (d < 0.5f);

            int rt = near ? 0 : (appr ? 1 : (flee ? 2 : (above ? 3 : best)));
            float co = conf;
            if (near)              co = fmaxf(co, 0.8f);
            else if (appr || flee) co = fmaxf(co, 0.6f);
            else if (above)        co = fmaxf(co, 0.5f);

            int ig = i0 + ty + p * 16;
            int jg = j0 + tx + q * 16;
            size_t off = (size_t)ig * NN_ + jg;
            out[off]             = (float)rt;
            out[PLANE + off]     = co;
            out[2 * PLANE + off] = (jg > ig && co > 0.3f) ? 1.0f : 0.0f;
        }
    }
}

extern "C" void kernel_launch(void* const* d_in, const int* in_sizes, int n_in,
                              void* d_out, int out_size)
{
    const float* E    = (const float*)d_in[0];
    const float* pos  = (const float*)d_in[1];
    const float* prev = (const float*)d_in[2];
    const float* W1   = (const float*)d_in[3];
    const float* b1   = (const float*)d_in[4];
    const float* W2   = (const float*)d_in[5];
    const float* b2   = (const float*)d_in[6];
    float* out = (float*)d_out;

    gemm_partial_kernel<<<dim3(24, KSPLIT), 256>>>(E, W1);
    fold_kernel<<<NN_ / 4, dim3(64, 4)>>>(pos, prev, W1, b1);
    pair_kernel<<<dim3(48, 48), dim3(16, 16)>>>(W1, W2, b2, out);
}